// round 16
// baseline (speedup 1.0000x reference)
#include <cuda_runtime.h>
#include <cstdint>

// out[n] = embedding[hash(trunc(x[n]*128))]  (reference's xf==0 collapses the
// trilerp to corner 0, weight 1; bit-exact).
// hash = (u0 ^ u1*2654435761 ^ u2*805459861) & (2^19 - 1)
//
// R16 = R14 verbatim (measured best: kernel 21.54us, bench 24.6us).
// The kernel sits at the B300 random-gather hardware floor: six mechanisms
// (LDG.128 / LDG.32 octet / cp.async / TMA bulk x2 / nc+ca split) all cap at
// ~0.36 random rows/cyc/SM => per-SM outstanding-sector pool ~87 @ ~248cyc
// L2 latency; 14.2K rows/SM / 0.36 ~= 40K cyc ~= 21.4us floor (100.6% hit).
// Shape: 8 lanes cooperatively gather one 32B row (1 sector/row, 4 rows per
// LDG.32 instruction, hashes distributed via shfl); evict_last policy keeps
// the 16MB table L2-resident; x/out use streaming (.cs) accesses; stores are
// fully coalesced (warp writes 4x128B per STG.32). ITERS=2, grid 4096 is the
// empirical optimum (ITERS=4/grid 2048 regressed to 22.3us in R15).

static constexpr unsigned P1 = 2654435761u;
static constexpr unsigned P2 = 805459861u;
static constexpr unsigned HASH_MASK = 524288u - 1u;  // 2^19
static constexpr int THREADS = 256;
static constexpr int PTS_PER_BLOCK = 512;            // 8 warps * 64 pts

__device__ __forceinline__ unsigned hash3f(float a, float b, float c)
{
    unsigned u0 = (unsigned)__float2int_rz(a * 128.0f);
    unsigned u1 = (unsigned)__float2int_rz(b * 128.0f);
    unsigned u2 = (unsigned)__float2int_rz(c * 128.0f);
    return (u0 ^ (u1 * P1) ^ (u2 * P2)) & HASH_MASK;
}

__device__ __forceinline__ float ld_table(const float* p, unsigned long long pol)
{
    float v;
    asm volatile("ld.global.nc.L2::cache_hint.b32 %0, [%1], %2;"
                 : "=f"(v) : "l"(p), "l"(pol));
    return v;
}

__device__ __forceinline__ float ld_stream(const float* p)
{
    float v;
    asm volatile("ld.global.cs.b32 %0, [%1];" : "=f"(v) : "l"(p));
    return v;
}

__device__ __forceinline__ void st_stream(float* p, float v)
{
    asm volatile("st.global.cs.b32 [%0], %1;" :: "l"(p), "f"(v) : "memory");
}

__global__ void __launch_bounds__(THREADS)
hashgrid_octet_pin_kernel(const float* __restrict__ x,
                          const float* __restrict__ embw,   // word view [H][8]
                          float* __restrict__ outw)         // word view [N][8]
{
    const int tid  = threadIdx.x;
    const int w    = tid >> 5;
    const int L    = tid & 31;
    const int sub  = L >> 3;   // which of 4 rows this lane helps gather
    const int word = L & 7;    // which 4B word of the 32B row

    // evict_last policy for the embedding table
    unsigned long long pol;
    asm volatile("createpolicy.fractional.L2::evict_last.b64 %0, 1.0;"
                 : "=l"(pol));

    const size_t wb = (size_t)blockIdx.x * PTS_PER_BLOCK + (size_t)w * 64;

    // ---- hash one point per lane, two iterations (64 pts per warp) ----
    unsigned h[2];
#pragma unroll
    for (int it = 0; it < 2; it++) {
        size_t p = wb + it * 32 + L;
        float a = ld_stream(&x[3 * p + 0]);
        float b = ld_stream(&x[3 * p + 1]);
        float c = ld_stream(&x[3 * p + 2]);
        h[it] = hash3f(a, b, c);
    }

    // ---- gather: 16 independent LDG.32, 4 rows per instruction,
    //      table lines pinned in L2 via evict_last policy ----
    float v[16];
#pragma unroll
    for (int it = 0; it < 2; it++) {
#pragma unroll
        for (int s = 0; s < 8; s++) {
            unsigned hs = __shfl_sync(0xFFFFFFFFu, h[it], 4 * s + sub);
            v[it * 8 + s] = ld_table(&embw[(size_t)hs * 8 + word], pol);
        }
    }

    // ---- stores: each STG.32 writes 128B contiguous (4 pts), evict-first ----
#pragma unroll
    for (int it = 0; it < 2; it++) {
#pragma unroll
        for (int s = 0; s < 8; s++) {
            size_t p = wb + it * 32 + 4 * s + sub;
            st_stream(&outw[p * 8 + word], v[it * 8 + s]);
        }
    }
}

// ---------------- fallback (proven R3) for non-multiple sizes ----------------

__global__ void __launch_bounds__(THREADS)
hashgrid_gather_ilp4_kernel(const float* __restrict__ x,
                            const float4* __restrict__ emb,
                            float4* __restrict__ out,
                            int n)
{
    int tid  = threadIdx.x;
    int w    = tid >> 5;
    int lane = tid & 31;
    int qw   = lane >> 1;
    int half = lane & 1;
    int base = blockIdx.x * PTS_PER_BLOCK + w * 64 + qw;

    float xv[4][3];
#pragma unroll
    for (int k = 0; k < 4; k++) {
        int p = base + 16 * k;
        if (p < n) {
            xv[k][0] = x[3 * p + 0];
            xv[k][1] = x[3 * p + 1];
            xv[k][2] = x[3 * p + 2];
        }
    }
    unsigned h[4];
#pragma unroll
    for (int k = 0; k < 4; k++)
        h[k] = hash3f(xv[k][0], xv[k][1], xv[k][2]);

    float4 v[4];
#pragma unroll
    for (int k = 0; k < 4; k++)
        if (base + 16 * k < n) v[k] = __ldg(&emb[2 * h[k] + half]);
#pragma unroll
    for (int k = 0; k < 4; k++) {
        int p = base + 16 * k;
        if (p < n) out[2 * p + half] = v[k];
    }
}

extern "C" void kernel_launch(void* const* d_in, const int* in_sizes, int n_in,
                              void* d_out, int out_size)
{
    const float* x   = (const float*)d_in[0];
    const float* emb = (const float*)d_in[1];
    float*       out = (float*)d_out;

    int n = in_sizes[0] / 3;  // N_POINTS

    if (n % PTS_PER_BLOCK == 0) {
        int blocks = n / PTS_PER_BLOCK;  // 4096
        hashgrid_octet_pin_kernel<<<blocks, THREADS>>>(x, emb, out);
    } else {
        int blocks = (n + PTS_PER_BLOCK - 1) / PTS_PER_BLOCK;
        hashgrid_gather_ilp4_kernel<<<blocks, THREADS>>>(
            x, (const float4*)emb, (float4*)out, n);
    }
}

// round 17
// speedup vs baseline: 1.0064x; 1.0064x over previous
#include <cuda_runtime.h>
#include <cstdint>

// out[n] = embedding[hash(trunc(x[n]*128))]  (reference's xf==0 collapses the
// trilerp to corner 0, weight 1; bit-exact).
// hash = (u0 ^ u1*2654435761 ^ u2*805459861) & (2^19 - 1)
//
// FINAL (R14/R16 shape, reproduced twice at kernel 21.2-21.5us):
// The kernel sits at the B300 random-gather hardware floor. Six mechanisms
// (LDG.128 / LDG.32 octet / cp.async / TMA bulk x2 / nc+ca split) all cap at
// ~0.36 random rows/cyc/SM => per-SM outstanding-sector pool ~87 @ ~248cyc
// L2 latency; 14.2K rows/SM / 0.36 ~= 40K cyc ~= 21.4us floor.
// Shape: 8 lanes cooperatively gather one 32B row (1 sector/row, 4 rows per
// LDG.32 instruction, hashes distributed via shfl); evict_last policy keeps
// the 16MB table L2-resident; x/out use streaming (.cs) accesses; stores are
// fully coalesced (warp writes 4x128B per STG.32). ITERS=2 / grid 4096 is
// the empirical optimum (ITERS=4 / grid 2048 regressed in R15).

static constexpr unsigned P1 = 2654435761u;
static constexpr unsigned P2 = 805459861u;
static constexpr unsigned HASH_MASK = 524288u - 1u;  // 2^19
static constexpr int THREADS = 256;
static constexpr int PTS_PER_BLOCK = 512;            // 8 warps * 64 pts

__device__ __forceinline__ unsigned hash3f(float a, float b, float c)
{
    unsigned u0 = (unsigned)__float2int_rz(a * 128.0f);
    unsigned u1 = (unsigned)__float2int_rz(b * 128.0f);
    unsigned u2 = (unsigned)__float2int_rz(c * 128.0f);
    return (u0 ^ (u1 * P1) ^ (u2 * P2)) & HASH_MASK;
}

__device__ __forceinline__ float ld_table(const float* p, unsigned long long pol)
{
    float v;
    asm volatile("ld.global.nc.L2::cache_hint.b32 %0, [%1], %2;"
                 : "=f"(v) : "l"(p), "l"(pol));
    return v;
}

__device__ __forceinline__ float ld_stream(const float* p)
{
    float v;
    asm volatile("ld.global.cs.b32 %0, [%1];" : "=f"(v) : "l"(p));
    return v;
}

__device__ __forceinline__ void st_stream(float* p, float v)
{
    asm volatile("st.global.cs.b32 [%0], %1;" :: "l"(p), "f"(v) : "memory");
}

__global__ void __launch_bounds__(THREADS)
hashgrid_octet_pin_kernel(const float* __restrict__ x,
                          const float* __restrict__ embw,   // word view [H][8]
                          float* __restrict__ outw)         // word view [N][8]
{
    const int tid  = threadIdx.x;
    const int w    = tid >> 5;
    const int L    = tid & 31;
    const int sub  = L >> 3;   // which of 4 rows this lane helps gather
    const int word = L & 7;    // which 4B word of the 32B row

    // evict_last policy for the embedding table
    unsigned long long pol;
    asm volatile("createpolicy.fractional.L2::evict_last.b64 %0, 1.0;"
                 : "=l"(pol));

    const size_t wb = (size_t)blockIdx.x * PTS_PER_BLOCK + (size_t)w * 64;

    // ---- hash one point per lane, two iterations (64 pts per warp) ----
    unsigned h[2];
#pragma unroll
    for (int it = 0; it < 2; it++) {
        size_t p = wb + it * 32 + L;
        float a = ld_stream(&x[3 * p + 0]);
        float b = ld_stream(&x[3 * p + 1]);
        float c = ld_stream(&x[3 * p + 2]);
        h[it] = hash3f(a, b, c);
    }

    // ---- gather: 16 independent LDG.32, 4 rows per instruction,
    //      table lines pinned in L2 via evict_last policy ----
    float v[16];
#pragma unroll
    for (int it = 0; it < 2; it++) {
#pragma unroll
        for (int s = 0; s < 8; s++) {
            unsigned hs = __shfl_sync(0xFFFFFFFFu, h[it], 4 * s + sub);
            v[it * 8 + s] = ld_table(&embw[(size_t)hs * 8 + word], pol);
        }
    }

    // ---- stores: each STG.32 writes 128B contiguous (4 pts), evict-first ----
#pragma unroll
    for (int it = 0; it < 2; it++) {
#pragma unroll
        for (int s = 0; s < 8; s++) {
            size_t p = wb + it * 32 + 4 * s + sub;
            st_stream(&outw[p * 8 + word], v[it * 8 + s]);
        }
    }
}

// ---------------- fallback (proven R3) for non-multiple sizes ----------------

__global__ void __launch_bounds__(THREADS)
hashgrid_gather_ilp4_kernel(const float* __restrict__ x,
                            const float4* __restrict__ emb,
                            float4* __restrict__ out,
                            int n)
{
    int tid  = threadIdx.x;
    int w    = tid >> 5;
    int lane = tid & 31;
    int qw   = lane >> 1;
    int half = lane & 1;
    int base = blockIdx.x * PTS_PER_BLOCK + w * 64 + qw;

    float xv[4][3];
#pragma unroll
    for (int k = 0; k < 4; k++) {
        int p = base + 16 * k;
        if (p < n) {
            xv[k][0] = x[3 * p + 0];
            xv[k][1] = x[3 * p + 1];
            xv[k][2] = x[3 * p + 2];
        }
    }
    unsigned h[4];
#pragma unroll
    for (int k = 0; k < 4; k++)
        h[k] = hash3f(xv[k][0], xv[k][1], xv[k][2]);

    float4 v[4];
#pragma unroll
    for (int k = 0; k < 4; k++)
        if (base + 16 * k < n) v[k] = __ldg(&emb[2 * h[k] + half]);
#pragma unroll
    for (int k = 0; k < 4; k++) {
        int p = base + 16 * k;
        if (p < n) out[2 * p + half] = v[k];
    }
}

extern "C" void kernel_launch(void* const* d_in, const int* in_sizes, int n_in,
                              void* d_out, int out_size)
{
    const float* x   = (const float*)d_in[0];
    const float* emb = (const float*)d_in[1];
    float*       out = (float*)d_out;

    int n = in_sizes[0] / 3;  // N_POINTS

    if (n % PTS_PER_BLOCK == 0) {
        int blocks = n / PTS_PER_BLOCK;  // 4096
        hashgrid_octet_pin_kernel<<<blocks, THREADS>>>(x, emb, out);
    } else {
        int blocks = (n + PTS_PER_BLOCK - 1) / PTS_PER_BLOCK;
        hashgrid_gather_ilp4_kernel<<<blocks, THREADS>>>(
            x, (const float4*)emb, (float4*)out, n);
    }
}